// round 1
// baseline (speedup 1.0000x reference)
#include <cuda_runtime.h>

// SlimMambaBlock on GB300 — Round 1: correctness-first fp32 SIMT baseline.
// Pipeline: rmsnorm -> GEMM1(+silu split u/z) -> GEMM2(+bias+sigmoid) ->
//           sequential scan (+ *silu(z)) -> GEMM3(+residual).
// All GEMMs are C[M,N] = A[M,K] * B[N,K]^T (both operands K-contiguous).

#define TM 128
#define TN 128
#define TK 16

#define MTOT   16384      // B*K = 8*2048
#define DDIM   1024
#define NINNER 2048

// Scratch (static device globals — no runtime allocation allowed).
__device__ float g_h  [(size_t)MTOT * DDIM];    //  67 MB  normalized input
__device__ float g_u  [(size_t)MTOT * NINNER];  // 134 MB  silu(u)
__device__ float g_zs [(size_t)MTOT * NINNER];  // 134 MB  silu(z)
__device__ float g_lam[(size_t)MTOT * NINNER];  // 134 MB  sigmoid gate
__device__ float g_s  [(size_t)MTOT * NINNER];  // 134 MB  scan out * silu(z)

__device__ __forceinline__ float sig_(float v)  { return 1.0f / (1.0f + __expf(-v)); }
__device__ __forceinline__ float silu_(float v) { return v * sig_(v); }

// ---------------------------------------------------------------------------
// RMSNorm: one block per row of 1024, 256 threads * float4
// ---------------------------------------------------------------------------
__global__ void rmsnorm_k(const float* __restrict__ x,
                          const float* __restrict__ w,
                          float* __restrict__ h)
{
    const int row = blockIdx.x;
    const int t   = threadIdx.x;
    const float4 v = ((const float4*)(x + (size_t)row * DDIM))[t];
    float ss = v.x * v.x + v.y * v.y + v.z * v.z + v.w * v.w;
    #pragma unroll
    for (int o = 16; o > 0; o >>= 1) ss += __shfl_xor_sync(0xffffffffu, ss, o);
    __shared__ float ws[8];
    if ((t & 31) == 0) ws[t >> 5] = ss;
    __syncthreads();
    const float tot = ws[0] + ws[1] + ws[2] + ws[3] + ws[4] + ws[5] + ws[6] + ws[7];
    const float inv = rsqrtf(tot * (1.0f / (float)DDIM) + 1e-5f);
    const float4 wv = ((const float4*)w)[t];
    float4 o4;
    o4.x = v.x * inv * wv.x;
    o4.y = v.y * inv * wv.y;
    o4.z = v.z * inv * wv.z;
    o4.w = v.w * inv * wv.w;
    ((float4*)(h + (size_t)row * DDIM))[t] = o4;
}

// ---------------------------------------------------------------------------
// Tiled fp32 GEMM: C = A[M,K] * B[N,K]^T, 128x128x16 block, 8x8 per thread.
// Thread fragment covers rows {tm4..tm4+3, tm4+64..tm4+67} and likewise cols,
// which keeps LDS.128 smem reads at the 2-phase minimum and the epilogue
// stores float4-coalesced.
// MODE 0: GEMM1  — silu(c); column < INNER -> out0 (u), else -> out1 (silu z)
// MODE 1: GEMM2  — sigmoid(c + aux[n]) -> out0 (lam)
// MODE 2: GEMM3  — c + aux[row*N+n] (residual x) -> out0 (final output)
// ---------------------------------------------------------------------------
template<int MODE>
__global__ __launch_bounds__(256, 2)
void gemm_tn(const float* __restrict__ A, const float* __restrict__ Bw,
             int N, int K,
             const float* __restrict__ aux,
             float* __restrict__ out0, float* __restrict__ out1)
{
    __shared__ float As[TK][TM];
    __shared__ float Bs[TK][TN];

    const int tid  = threadIdx.x;
    const int bm   = blockIdx.y * TM;
    const int bn   = blockIdx.x * TN;
    const int lrow = tid >> 2;            // 0..63
    const int lc4  = (tid & 3) << 2;      // 0,4,8,12
    const int tm4  = (tid >> 4) << 2;     // 0..60
    const int tn4  = (tid & 15) << 2;     // 0..60

    float acc[8][8];
    #pragma unroll
    for (int i = 0; i < 8; i++)
        #pragma unroll
        for (int j = 0; j < 8; j++) acc[i][j] = 0.0f;

    const float* Aptr0 = A  + (size_t)(bm + lrow)      * K + lc4;
    const float* Aptr1 = A  + (size_t)(bm + lrow + 64) * K + lc4;
    const float* Bptr0 = Bw + (size_t)(bn + lrow)      * K + lc4;
    const float* Bptr1 = Bw + (size_t)(bn + lrow + 64) * K + lc4;

    // prefetch first K-tile into registers
    float4 ra0 = *(const float4*)(Aptr0);
    float4 ra1 = *(const float4*)(Aptr1);
    float4 rb0 = *(const float4*)(Bptr0);
    float4 rb1 = *(const float4*)(Bptr1);

    for (int kt = 0; kt < K; kt += TK) {
        As[lc4 + 0][lrow]      = ra0.x; As[lc4 + 1][lrow]      = ra0.y;
        As[lc4 + 2][lrow]      = ra0.z; As[lc4 + 3][lrow]      = ra0.w;
        As[lc4 + 0][lrow + 64] = ra1.x; As[lc4 + 1][lrow + 64] = ra1.y;
        As[lc4 + 2][lrow + 64] = ra1.z; As[lc4 + 3][lrow + 64] = ra1.w;
        Bs[lc4 + 0][lrow]      = rb0.x; Bs[lc4 + 1][lrow]      = rb0.y;
        Bs[lc4 + 2][lrow]      = rb0.z; Bs[lc4 + 3][lrow]      = rb0.w;
        Bs[lc4 + 0][lrow + 64] = rb1.x; Bs[lc4 + 1][lrow + 64] = rb1.y;
        Bs[lc4 + 2][lrow + 64] = rb1.z; Bs[lc4 + 3][lrow + 64] = rb1.w;
        __syncthreads();

        if (kt + TK < K) {  // prefetch next tile (overlaps with compute below)
            ra0 = *(const float4*)(Aptr0 + kt + TK);
            ra1 = *(const float4*)(Aptr1 + kt + TK);
            rb0 = *(const float4*)(Bptr0 + kt + TK);
            rb1 = *(const float4*)(Bptr1 + kt + TK);
        }

        #pragma unroll
        for (int kk = 0; kk < TK; kk++) {
            float a[8], b[8];
            *(float4*)(a)     = *(const float4*)&As[kk][tm4];
            *(float4*)(a + 4) = *(const float4*)&As[kk][tm4 + 64];
            *(float4*)(b)     = *(const float4*)&Bs[kk][tn4];
            *(float4*)(b + 4) = *(const float4*)&Bs[kk][tn4 + 64];
            #pragma unroll
            for (int i = 0; i < 8; i++)
                #pragma unroll
                for (int j = 0; j < 8; j++)
                    acc[i][j] = fmaf(a[i], b[j], acc[i][j]);
        }
        __syncthreads();
    }

    // epilogue
    #pragma unroll
    for (int i = 0; i < 8; i++) {
        const int row = bm + tm4 + ((i < 4) ? i : (60 + i));
        #pragma unroll
        for (int jh = 0; jh < 2; jh++) {
            const int col = bn + tn4 + jh * 64;
            float c0 = acc[i][jh * 4 + 0];
            float c1 = acc[i][jh * 4 + 1];
            float c2 = acc[i][jh * 4 + 2];
            float c3 = acc[i][jh * 4 + 3];
            float4 v;
            if (MODE == 0) {
                v.x = silu_(c0); v.y = silu_(c1); v.z = silu_(c2); v.w = silu_(c3);
                const bool isu = (bn < NINNER);
                float* dst = isu ? out0 : out1;
                const int c = col - (isu ? 0 : NINNER);
                *(float4*)(dst + (size_t)row * NINNER + c) = v;
            } else if (MODE == 1) {
                v.x = sig_(c0 + aux[col + 0]);
                v.y = sig_(c1 + aux[col + 1]);
                v.z = sig_(c2 + aux[col + 2]);
                v.w = sig_(c3 + aux[col + 3]);
                *(float4*)(out0 + (size_t)row * N + col) = v;
            } else {
                const float4 xv = *(const float4*)(aux + (size_t)row * N + col);
                v.x = c0 + xv.x; v.y = c1 + xv.y; v.z = c2 + xv.z; v.w = c3 + xv.w;
                *(float4*)(out0 + (size_t)row * N + col) = v;
            }
        }
    }
}

// ---------------------------------------------------------------------------
// Sequential gated scan: one thread per (batch, channel) chain.
//   s_k = lam_k * s_{k-1} + (1-lam_k) * u_k ;  out_k = s_k * silu(z)_k
// Coalesced across channels at each k step.
// ---------------------------------------------------------------------------
__global__ void scan_k(const float* __restrict__ lam, const float* __restrict__ u,
                       const float* __restrict__ zs,  float* __restrict__ so)
{
    const int gid = blockIdx.x * blockDim.x + threadIdx.x;  // 0..16383
    const int b = gid >> 11;           // batch
    const int i = gid & 2047;          // channel
    size_t idx = (size_t)b * (2048u * 2048u) + i;
    float s = 0.0f;
    #pragma unroll 8
    for (int k = 0; k < 2048; k++) {
        const float l  = lam[idx];
        const float uu = u[idx];
        s = fmaf(l, s - uu, uu);       // l*s + (1-l)*u
        so[idx] = s * zs[idx];
        idx += NINNER;
    }
}

// ---------------------------------------------------------------------------
extern "C" void kernel_launch(void* const* d_in, const int* in_sizes, int n_in,
                              void* d_out, int out_size)
{
    const float* x      = (const float*)d_in[0];  // [8,2048,1024]
    const float* w_norm = (const float*)d_in[1];  // [1024]
    const float* W_in   = (const float*)d_in[2];  // [4096,1024]
    const float* W_dt   = (const float*)d_in[3];  // [2048,2048]
    const float* b_dt   = (const float*)d_in[4];  // [2048]
    const float* W_out  = (const float*)d_in[5];  // [1024,2048]
    float* out = (float*)d_out;                   // [8,2048,1024]

    float *h, *u, *zs, *lam, *s;
    cudaGetSymbolAddress((void**)&h,   g_h);
    cudaGetSymbolAddress((void**)&u,   g_u);
    cudaGetSymbolAddress((void**)&zs,  g_zs);
    cudaGetSymbolAddress((void**)&lam, g_lam);
    cudaGetSymbolAddress((void**)&s,   g_s);

    rmsnorm_k<<<MTOT, 256>>>(x, w_norm, h);

    // uv = h @ W_in^T ; u=silu(uv[:,:2048]) ; zs=silu(uv[:,2048:])
    gemm_tn<0><<<dim3(4096 / TN, MTOT / TM), 256>>>(h, W_in, 4096, 1024,
                                                    nullptr, u, zs);
    // lam = sigmoid(u @ W_dt^T + b_dt)
    gemm_tn<1><<<dim3(2048 / TN, MTOT / TM), 256>>>(u, W_dt, 2048, 2048,
                                                    b_dt, lam, nullptr);
    // gated scan + multiply by silu(z)
    scan_k<<<MTOT / 256, 256>>>(lam, u, zs, s);

    // y = s @ W_out^T ; out = x + y
    gemm_tn<2><<<dim3(1024 / TN, MTOT / TM), 256>>>(s, W_out, 1024, 2048,
                                                    x, out, nullptr);
}

// round 5
// speedup vs baseline: 1.9974x; 1.9974x over previous
#include <cuda_runtime.h>
#include <cuda_bf16.h>
#include <cstdint>

// SlimMambaBlock GB300 R5: mma.sync (HMMA) bf16 3-term split GEMMs.
// (R4 resubmission — broker timeout, never ran. Audit re-verified fragment
// layouts, swizzle algebra, cp.async pipeline.)
// tcgen05 is unavailable (ptxas targets base sm_103, no 'a' features).
// fp32 x = hi(bf16) + lo(bf16);  A*B ~= Ah*Bh + Ah*Bl + Al*Bh  (fp32 acc)

#define MTOT   16384
#define DDIM   1024
#define NINNER 2048
#define KC     64                 // K elems per chunk (64 bf16 = 128B row)
#define STAGEB 65536               // 4 sub-tiles * 16KB
#define SMB    (2 * STAGEB)        // double buffer

// ---------------- scratch (static device globals) ----------------
__device__ __nv_bfloat16 g_hh [(size_t)MTOT * DDIM];
__device__ __nv_bfloat16 g_hl [(size_t)MTOT * DDIM];
__device__ __nv_bfloat16 g_uh [(size_t)MTOT * NINNER];
__device__ __nv_bfloat16 g_ul [(size_t)MTOT * NINNER];
__device__ float         g_zs [(size_t)MTOT * NINNER];
__device__ float         g_lam[(size_t)MTOT * NINNER];
__device__ __nv_bfloat16 g_sh [(size_t)MTOT * NINNER];
__device__ __nv_bfloat16 g_sl [(size_t)MTOT * NINNER];
__device__ __nv_bfloat16 g_w1h[(size_t)2 * NINNER * DDIM];
__device__ __nv_bfloat16 g_w1l[(size_t)2 * NINNER * DDIM];
__device__ __nv_bfloat16 g_w2h[(size_t)NINNER * NINNER];
__device__ __nv_bfloat16 g_w2l[(size_t)NINNER * NINNER];
__device__ __nv_bfloat16 g_w3h[(size_t)DDIM * NINNER];
__device__ __nv_bfloat16 g_w3l[(size_t)DDIM * NINNER];

// ---------------- helpers ----------------
__device__ __forceinline__ uint32_t smem_u32(const void* p) {
    uint32_t a;
    asm("{ .reg .u64 t; cvta.to.shared.u64 t, %1; cvt.u32.u64 %0, t; }" : "=r"(a) : "l"(p));
    return a;
}
#define CP16(d, s)  asm volatile("cp.async.cg.shared.global [%0], [%1], 16;" :: "r"(d), "l"(s))
#define CPCOMMIT()  asm volatile("cp.async.commit_group;" ::: "memory")
#define CPWAIT(N)   asm volatile("cp.async.wait_group %0;" :: "n"(N) : "memory")
#define LDSM4(R, A) asm volatile("ldmatrix.sync.aligned.m8n8.x4.shared.b16 {%0,%1,%2,%3}, [%4];" \
    : "=r"((R)[0]), "=r"((R)[1]), "=r"((R)[2]), "=r"((R)[3]) : "r"(A))
#define MMA(D, A4, B0, B1) asm volatile( \
    "mma.sync.aligned.m16n8k16.row.col.f32.bf16.bf16.f32 " \
    "{%0,%1,%2,%3}, {%4,%5,%6,%7}, {%8,%9}, {%0,%1,%2,%3};" \
    : "+f"((D)[0]), "+f"((D)[1]), "+f"((D)[2]), "+f"((D)[3]) \
    : "r"((A4)[0]), "r"((A4)[1]), "r"((A4)[2]), "r"((A4)[3]), "r"(B0), "r"(B1))

__device__ __forceinline__ float sig_(float v)  { return 1.0f / (1.0f + __expf(-v)); }
__device__ __forceinline__ float silu_(float v) { return v * sig_(v); }
__device__ __forceinline__ void split_(float v, __nv_bfloat16& h, __nv_bfloat16& l) {
    h = __float2bfloat16(v);
    l = __float2bfloat16(v - __bfloat162float(h));
}

// ---------------------------------------------------------------------------
__global__ void conv_hilo(const float* __restrict__ src,
                          __nv_bfloat16* __restrict__ hi,
                          __nv_bfloat16* __restrict__ lo, int n4)
{
    int i = blockIdx.x * blockDim.x + threadIdx.x;
    if (i >= n4) return;
    const float4 v = ((const float4*)src)[i];
    union { __nv_bfloat16 b[4]; uint2 u; } H, L;
    split_(v.x, H.b[0], L.b[0]); split_(v.y, H.b[1], L.b[1]);
    split_(v.z, H.b[2], L.b[2]); split_(v.w, H.b[3], L.b[3]);
    ((uint2*)hi)[i] = H.u;  ((uint2*)lo)[i] = L.u;
}

__global__ void rmsnorm_k(const float* __restrict__ x, const float* __restrict__ w,
                          __nv_bfloat16* __restrict__ hh, __nv_bfloat16* __restrict__ hl)
{
    const int row = blockIdx.x;
    const int t   = threadIdx.x;
    const float4 v = ((const float4*)(x + (size_t)row * DDIM))[t];
    float ss = v.x * v.x + v.y * v.y + v.z * v.z + v.w * v.w;
    #pragma unroll
    for (int o = 16; o > 0; o >>= 1) ss += __shfl_xor_sync(0xffffffffu, ss, o);
    __shared__ float ws[8];
    if ((t & 31) == 0) ws[t >> 5] = ss;
    __syncthreads();
    const float tot = ws[0]+ws[1]+ws[2]+ws[3]+ws[4]+ws[5]+ws[6]+ws[7];
    const float inv = rsqrtf(tot * (1.0f / (float)DDIM) + 1e-5f);
    const float4 wv = ((const float4*)w)[t];
    union { __nv_bfloat16 b[4]; uint2 u; } H, L;
    split_(v.x * inv * wv.x, H.b[0], L.b[0]);
    split_(v.y * inv * wv.y, H.b[1], L.b[1]);
    split_(v.z * inv * wv.z, H.b[2], L.b[2]);
    split_(v.w * inv * wv.w, H.b[3], L.b[3]);
    ((uint2*)(hh + (size_t)row * DDIM))[t] = H.u;
    ((uint2*)(hl + (size_t)row * DDIM))[t] = L.u;
}

// ---------------------------------------------------------------------------
// HMMA GEMM: C[128,128] tile of A[M,K]*B[N,K]^T, 3-term bf16 split.
// 8 warps as 2(M) x 4(N); warp tile 64x32; mma m16n8k16.
// MODE 0: GEMM1  cols<2048 -> silu -> u hi/lo ; cols>=2048 -> silu -> zs(f32)
// MODE 1: GEMM2  sigmoid(c + aux[col]) -> fout
// MODE 2: GEMM3  c + aux[row*outN+col] -> fout
// ---------------------------------------------------------------------------
template<int MODE>
__global__ __launch_bounds__(256, 1)
void gemm_mma(const __nv_bfloat16* __restrict__ Ahi, const __nv_bfloat16* __restrict__ Alo,
              const __nv_bfloat16* __restrict__ Bhi, const __nv_bfloat16* __restrict__ Blo,
              int K, const float* __restrict__ aux,
              float* __restrict__ fout,
              __nv_bfloat16* __restrict__ bhout, __nv_bfloat16* __restrict__ blout,
              int outN)
{
    extern __shared__ char smem[];
    const uint32_t sb = smem_u32(smem);
    const int tid  = threadIdx.x;
    const int lane = tid & 31;
    const int wid  = tid >> 5;
    const int wm   = (wid & 1) * 64;     // warp M offset in tile
    const int wn   = (wid >> 1) * 32;    // warp N offset in tile
    const int bm   = blockIdx.y * 128;
    const int bn   = blockIdx.x * 128;

    // -------- gmem->smem loader precompute (4 chunks per sub-tile/thread)
    const char* gsrc[4] = {
        (const char*)(Ahi + (size_t)bm * K), (const char*)(Alo + (size_t)bm * K),
        (const char*)(Bhi + (size_t)bn * K), (const char*)(Blo + (size_t)bn * K) };
    uint32_t sdst[4];
    size_t   goff[4];
    #pragma unroll
    for (int j = 0; j < 4; j++) {
        const int c = tid + j * 256;          // 0..1023
        const int row = c >> 3, slot = c & 7;
        const uint32_t off = row * 128 + slot * 16;
        sdst[j] = off ^ ((off >> 3) & 0x70);
        goff[j] = (size_t)row * ((size_t)K * 2) + slot * 16;
    }

    // -------- ldmatrix fragment address precompute (SW128-folded)
    // A frag x4 groups: g0=(m0-7,k0) g1=(m8-15,k0) g2=(m0-7,k8) g3=(m8-15,k8)
    // B frag x4 groups: g0=(n0-7,k0) g1=(n0-7,k8) g2=(n8-15,k0) g3=(n8-15,k8)
    const int gi = lane >> 3, rl = lane & 7;
    const uint32_t xh  = ((uint32_t)rl << 4) & 0x60;       // swizzle bits 5-6
    const uint32_t x4b = ((uint32_t)(rl & 1)) << 4;        // swizzle bit 4
    uint32_t pA[4], pB[2];
    #pragma unroll
    for (int mt = 0; mt < 4; mt++) {
        const int rr = wm + mt * 16 + ((gi & 1) << 3) + rl;
        pA[mt] = (uint32_t)rr * 128 + ((((uint32_t)(gi >> 1)) << 4) ^ x4b);
    }
    #pragma unroll
    for (int nt2 = 0; nt2 < 2; nt2++) {
        const int nr = wn + nt2 * 16 + ((gi >> 1) << 3) + rl;
        pB[nt2] = (uint32_t)nr * 128 + ((((uint32_t)(gi & 1)) << 4) ^ x4b);
    }

    float acc[4][4][4];
    #pragma unroll
    for (int a = 0; a < 4; a++)
        #pragma unroll
        for (int b = 0; b < 4; b++)
            #pragma unroll
            for (int d = 0; d < 4; d++) acc[a][b][d] = 0.0f;

    const int nch = K / KC;

    // prologue: stage 0
    {
        const uint32_t s0 = sb;
        #pragma unroll
        for (int w = 0; w < 4; w++)
            #pragma unroll
            for (int j = 0; j < 4; j++)
                CP16(s0 + w * 16384 + sdst[j], gsrc[w] + goff[j]);
        CPCOMMIT();
    }

    for (int c = 0; c < nch; c++) {
        const int st = c & 1;
        if (c + 1 < nch) {                       // issue next stage
            const uint32_t s1 = sb + (st ^ 1) * STAGEB;
            const size_t kb = (size_t)(c + 1) * (KC * 2);
            #pragma unroll
            for (int w = 0; w < 4; w++)
                #pragma unroll
                for (int j = 0; j < 4; j++)
                    CP16(s1 + w * 16384 + sdst[j], gsrc[w] + goff[j] + kb);
            CPCOMMIT();
            CPWAIT(1);
        } else {
            CPWAIT(0);
        }
        __syncthreads();

        const uint32_t s0 = sb + st * STAGEB;
        #pragma unroll
        for (int ks = 0; ks < 4; ks++) {
            const uint32_t kt = ((uint32_t)ks << 5) ^ xh;
            uint32_t ah[4][4], al[4][4], bh[2][4], bl[2][4];
            #pragma unroll
            for (int mt = 0; mt < 4; mt++) {
                LDSM4(ah[mt], s0 +         pA[mt] + kt);
                LDSM4(al[mt], s0 + 16384 + pA[mt] + kt);
            }
            #pragma unroll
            for (int nt2 = 0; nt2 < 2; nt2++) {
                LDSM4(bh[nt2], s0 + 32768 + pB[nt2] + kt);
                LDSM4(bl[nt2], s0 + 49152 + pB[nt2] + kt);
            }
            #pragma unroll
            for (int mt = 0; mt < 4; mt++)
                #pragma unroll
                for (int nt = 0; nt < 4; nt++) {
                    const int h2 = nt >> 1, o2 = (nt & 1) * 2;
                    MMA(acc[mt][nt], ah[mt], bh[h2][o2], bh[h2][o2 + 1]);
                    MMA(acc[mt][nt], ah[mt], bl[h2][o2], bl[h2][o2 + 1]);
                    MMA(acc[mt][nt], al[mt], bh[h2][o2], bh[h2][o2 + 1]);
                }
        }
        __syncthreads();
    }

    // -------- fused epilogue (register frags -> gmem)
    #pragma unroll
    for (int mt = 0; mt < 4; mt++) {
        #pragma unroll
        for (int half = 0; half < 2; half++) {
            const int row = bm + wm + mt * 16 + (lane >> 2) + half * 8;
            #pragma unroll
            for (int nt = 0; nt < 4; nt++) {
                const float v0 = acc[mt][nt][half * 2 + 0];
                const float v1 = acc[mt][nt][half * 2 + 1];
                const int col = bn + wn + nt * 8 + ((lane & 3) << 1);
                if (MODE == 0) {
                    const float s0 = silu_(v0), s1 = silu_(v1);
                    if (bn < NINNER) {
                        __nv_bfloat16 h0, l0, h1, l1;
                        split_(s0, h0, l0); split_(s1, h1, l1);
                        union { __nv_bfloat16 b[2]; uint32_t u; } H, L;
                        H.b[0] = h0; H.b[1] = h1; L.b[0] = l0; L.b[1] = l1;
                        const size_t o = (size_t)row * NINNER + col;
                        *(uint32_t*)(bhout + o) = H.u;
                        *(uint32_t*)(blout + o) = L.u;
                    } else {
                        const size_t o = (size_t)row * NINNER + (col - NINNER);
                        *(float2*)(fout + o) = make_float2(s0, s1);
                    }
                } else if (MODE == 1) {
                    const float2 bb = *(const float2*)(aux + col);
                    const size_t o = (size_t)row * outN + col;
                    *(float2*)(fout + o) = make_float2(sig_(v0 + bb.x), sig_(v1 + bb.y));
                } else {
                    const size_t o = (size_t)row * outN + col;
                    const float2 xv = *(const float2*)(aux + o);
                    *(float2*)(fout + o) = make_float2(v0 + xv.x, v1 + xv.y);
                }
            }
        }
    }
}

// ---------------------------------------------------------------------------
// Sequential gated scan; 512 CTAs x 32 threads spreads chains over all SMs.
// ---------------------------------------------------------------------------
__global__ void scan_k(const float* __restrict__ lam,
                       const __nv_bfloat16* __restrict__ uh,
                       const __nv_bfloat16* __restrict__ ul,
                       const float* __restrict__ zs,
                       __nv_bfloat16* __restrict__ sh,
                       __nv_bfloat16* __restrict__ sl)
{
    const int gid = blockIdx.x * blockDim.x + threadIdx.x;
    const int b = gid >> 11;
    const int i = gid & 2047;
    size_t idx = (size_t)b * ((size_t)2048 * NINNER) + i;
    float s = 0.0f;
    #pragma unroll 8
    for (int k = 0; k < 2048; k++) {
        const float l  = lam[idx];
        const float uu = __bfloat162float(uh[idx]) + __bfloat162float(ul[idx]);
        s = fmaf(l, s - uu, uu);
        const float v = s * zs[idx];
        __nv_bfloat16 h, lo2;
        split_(v, h, lo2);
        sh[idx] = h; sl[idx] = lo2;
        idx += NINNER;
    }
}

// ---------------------------------------------------------------------------
extern "C" void kernel_launch(void* const* d_in, const int* in_sizes, int n_in,
                              void* d_out, int out_size)
{
    const float* x      = (const float*)d_in[0];
    const float* w_norm = (const float*)d_in[1];
    const float* W_in   = (const float*)d_in[2];
    const float* W_dt   = (const float*)d_in[3];
    const float* b_dt   = (const float*)d_in[4];
    const float* W_out  = (const float*)d_in[5];
    float* out = (float*)d_out;

    __nv_bfloat16 *hh, *hl, *uh, *ul, *sh, *sl, *w1h, *w1l, *w2h, *w2l, *w3h, *w3l;
    float *zs, *lam;
    cudaGetSymbolAddress((void**)&hh,  g_hh);  cudaGetSymbolAddress((void**)&hl,  g_hl);
    cudaGetSymbolAddress((void**)&uh,  g_uh);  cudaGetSymbolAddress((void**)&ul,  g_ul);
    cudaGetSymbolAddress((void**)&zs,  g_zs);  cudaGetSymbolAddress((void**)&lam, g_lam);
    cudaGetSymbolAddress((void**)&sh,  g_sh);  cudaGetSymbolAddress((void**)&sl,  g_sl);
    cudaGetSymbolAddress((void**)&w1h, g_w1h); cudaGetSymbolAddress((void**)&w1l, g_w1l);
    cudaGetSymbolAddress((void**)&w2h, g_w2h); cudaGetSymbolAddress((void**)&w2l, g_w2l);
    cudaGetSymbolAddress((void**)&w3h, g_w3h); cudaGetSymbolAddress((void**)&w3l, g_w3l);

    cudaFuncSetAttribute(gemm_mma<0>, cudaFuncAttributeMaxDynamicSharedMemorySize, SMB);
    cudaFuncSetAttribute(gemm_mma<1>, cudaFuncAttributeMaxDynamicSharedMemorySize, SMB);
    cudaFuncSetAttribute(gemm_mma<2>, cudaFuncAttributeMaxDynamicSharedMemorySize, SMB);

    conv_hilo<<<(2*NINNER*DDIM/4 + 255)/256, 256>>>(W_in,  w1h, w1l, 2*NINNER*DDIM/4);
    conv_hilo<<<(NINNER*NINNER/4 + 255)/256, 256>>>(W_dt,  w2h, w2l, NINNER*NINNER/4);
    conv_hilo<<<(DDIM*NINNER/4   + 255)/256, 256>>>(W_out, w3h, w3l, DDIM*NINNER/4);

    rmsnorm_k<<<MTOT, 256>>>(x, w_norm, hh, hl);

    // GEMM1: uv = h @ W_in^T ; silu-split into u(hi/lo) and zs
    gemm_mma<0><<<dim3(32, MTOT/128), 256, SMB>>>(hh, hl, w1h, w1l, DDIM,
                                                  nullptr, zs, uh, ul, NINNER);
    // GEMM2: lam = sigmoid(u @ W_dt^T + b_dt)
    gemm_mma<1><<<dim3(16, MTOT/128), 256, SMB>>>(uh, ul, w2h, w2l, NINNER,
                                                  b_dt, lam, nullptr, nullptr, NINNER);
    // scan + *silu(z) -> s hi/lo
    scan_k<<<512, 32>>>(lam, uh, ul, zs, sh, sl);

    // GEMM3: out = x + s @ W_out^T
    gemm_mma<2><<<dim3(8, MTOT/128), 256, SMB>>>(sh, sl, w3h, w3l, NINNER,
                                                 x, out, nullptr, nullptr, DDIM);
}